// round 8
// baseline (speedup 1.0000x reference)
#include <cuda_runtime.h>
#include <cuda_fp16.h>

#define D     128
#define ROWS  128
#define TPB   512
#define SPT   132            // sPiT row stride (padded, %4==0 for float4)
#define SVS   129            // sV   row stride (odd: spreads column-store banks)

// shared memory layout (floats)
#define OFF_PIT 0            // sPiT[k*SPT + j]   (reused as sV[j*SVS + r] after GEMM1)
#define OFF_PI  16896        // sPi [j*D   + k]
#define OFF_X   33280        // sX  [k*D   + r]   (x * invnorm, transposed)
#define OFF_NQ  49664        // sNq [r]
#define SMEM_FLOATS 49792    // 199,168 bytes

typedef unsigned long long ull;

union F4U { float4 f4; ull u[2]; float s[4]; };

__device__ __forceinline__ ull dup2(float v) {
    ull r; unsigned u = __float_as_uint(v);
    asm("mov.b64 %0, {%1, %1};" : "=l"(r) : "r"(u));
    return r;
}
__device__ __forceinline__ void ffma2(ull& d, ull a, ull b) {
    asm("fma.rn.f32x2 %0, %1, %2, %3;" : "=l"(d) : "l"(a), "l"(b), "l"(d));
}
__device__ __forceinline__ void fmul2(ull& d, ull a, ull b) {
    asm("mul.rn.f32x2 %0, %1, %2;" : "=l"(d) : "l"(a), "l"(b));
}
__device__ __forceinline__ void unpack2(ull v, float& a, float& b) {
    unsigned ua, ub;
    asm("mov.b64 {%0, %1}, %2;" : "=r"(ua), "=r"(ub) : "l"(v));
    a = __uint_as_float(ua); b = __uint_as_float(ub);
}

__global__ void __launch_bounds__(TPB, 1)
tq_kernel(const float* __restrict__ x, const float* __restrict__ Pi,
          const float* __restrict__ cen, const float* __restrict__ bnd,
          float* __restrict__ out)
{
    extern __shared__ float sm[];
    float* sPiT = sm + OFF_PIT;
    float* sV   = sm + OFF_PIT;   // overlays sPiT (dead after GEMM1)
    float* sPi  = sm + OFF_PI;
    float* sX   = sm + OFF_X;
    float* sNq  = sm + OFF_NQ;

    const int tid = threadIdx.x;

    // ---- codebook -> registers: interior boundaries + centroid deltas ----
    float B[15], Dl[15];
    const float c0 = cen[0];
    {
        float prev = c0;
#pragma unroll
        for (int i = 0; i < 15; i++) {
            B[i]  = bnd[i + 1];
            float c = cen[i + 1];
            Dl[i] = c - prev;
            prev  = c;
        }
    }

    // ---- load Pi: row-major copy + padded transpose ----
#pragma unroll
    for (int i = 0; i < 8; i++) {
        int idx = tid + i * TPB;                 // float4 index over 4096
        ((float4*)sPi)[idx] = ((const float4*)Pi)[idx];
    }
#pragma unroll
    for (int i = 0; i < 32; i++) {
        int idx = tid + i * TPB;                 // scalar index over 16384
        int j = idx >> 7, k = idx & 127;
        sPiT[k * SPT + j] = Pi[idx];
    }

    // ---- load x tile (4 threads/row), norms, store x*invn transposed [k][r] ----
    {
        const int r = tid >> 2, h = tid & 3;     // h selects 32-float chunk
        const float4* xr = (const float4*)(x + ((size_t)blockIdx.x * ROWS + r) * D + h * 32);
        float4 xv[8];
        float ss = 0.f;
#pragma unroll
        for (int i = 0; i < 8; i++) {
            xv[i] = xr[i];
            ss += xv[i].x * xv[i].x + xv[i].y * xv[i].y
                + xv[i].z * xv[i].z + xv[i].w * xv[i].w;
        }
        ss += __shfl_xor_sync(0xffffffffu, ss, 1);
        ss += __shfl_xor_sync(0xffffffffu, ss, 2);
        float norm = sqrtf(ss);
        float invn = 1.0f / (norm + 1e-8f);
        if (h == 0) sNq[r] = __half2float(__float2half(norm));  // fp16 round trip
#pragma unroll
        for (int i = 0; i < 8; i++) {
            int k0 = h * 32 + i * 4;
            sX[(k0    ) * D + r] = xv[i].x * invn;
            sX[(k0 + 1) * D + r] = xv[i].y * invn;
            sX[(k0 + 2) * D + r] = xv[i].z * invn;
            sX[(k0 + 3) * D + r] = xv[i].w * invn;
        }
    }
    __syncthreads();

    // 4x8 per-thread tile:
    //   rows: {r0..r0+3},               r0 = 4*(tid>>4)   (32 groups x 4 = 128)
    //   cols: {c0..c0+3} U {64+c0..},   c0 = 4*(tid&15)
    const int tx  = tid & 15;
    const int ty  = tid >> 4;
    const int r0  = ty * 4;
    const int c0_ = tx * 4;

    // acc[p][q]: p = row (0-3), q = col-pair
    //   q=0: cols c0,c0+1   q=1: c0+2,c0+3   q=2: 64+c0,64+c0+1   q=3: 64+c0+2,64+c0+3
    ull acc[4][4];
#pragma unroll
    for (int p = 0; p < 4; p++)
#pragma unroll
        for (int q = 0; q < 4; q++) acc[p][q] = 0ull;

    // ---- GEMM1: rotated[r][j] = sum_k sX[k][r] * PiT[k][j] ----
#pragma unroll 4
    for (int k = 0; k < D; k++) {
        F4U a0; a0.f4 = *(const float4*)(sX + k * D + r0);
        const float* pk = sPiT + k * SPT;
        F4U b0, b1;
        b0.f4 = *(const float4*)(pk + c0_);
        b1.f4 = *(const float4*)(pk + 64 + c0_);
        ull ad[4];
#pragma unroll
        for (int p = 0; p < 4; p++) ad[p] = dup2(a0.s[p]);
#pragma unroll
        for (int p = 0; p < 4; p++) {
            ffma2(acc[p][0], ad[p], b0.u[0]);
            ffma2(acc[p][1], ad[p], b0.u[1]);
            ffma2(acc[p][2], ad[p], b1.u[0]);
            ffma2(acc[p][3], ad[p], b1.u[1]);
        }
    }
    __syncthreads();   // all reads of sPiT / sX complete before sV overwrite

    // ---- quantize (Lloyd-Max bucketize, side='left') & store sV[j][r] ----
#pragma unroll
    for (int p = 0; p < 4; p++) {
        const int r = r0 + p;
#pragma unroll
        for (int q = 0; q < 4; q++) {
            const int j0 = c0_ + (q & 1) * 2 + (q >> 1) * 64;
            float v0, v1;
            unpack2(acc[p][q], v0, v1);
            float w0 = c0, w1 = c0;
#pragma unroll
            for (int i = 0; i < 15; i++) {
                if (v0 > B[i]) w0 += Dl[i];
                if (v1 > B[i]) w1 += Dl[i];
            }
            sV[(j0    ) * SVS + r] = w0;
            sV[(j0 + 1) * SVS + r] = w1;
        }
    }
    __syncthreads();

    // ---- GEMM2: recon[r][k] = sum_j sV[j][r] * Pi[j][k] ----
#pragma unroll
    for (int p = 0; p < 4; p++)
#pragma unroll
        for (int q = 0; q < 4; q++) acc[p][q] = 0ull;

#pragma unroll 4
    for (int j = 0; j < D; j++) {
        const float* vj = sV + j * SVS;            // SVS odd -> SCALAR broadcast loads
        const float* pj = sPi + j * D;
        F4U b0, b1;
        b0.f4 = *(const float4*)(pj + c0_);
        b1.f4 = *(const float4*)(pj + 64 + c0_);
        ull ad[4];
#pragma unroll
        for (int p = 0; p < 4; p++) ad[p] = dup2(vj[r0 + p]);
#pragma unroll
        for (int p = 0; p < 4; p++) {
            ffma2(acc[p][0], ad[p], b0.u[0]);
            ffma2(acc[p][1], ad[p], b0.u[1]);
            ffma2(acc[p][2], ad[p], b1.u[0]);
            ffma2(acc[p][3], ad[p], b1.u[1]);
        }
    }

    // ---- epilogue: scale by fp16-roundtripped norm, vectorized store ----
    const size_t obase = (size_t)blockIdx.x * ROWS * D;
#pragma unroll
    for (int p = 0; p < 4; p++) {
        const int r = r0 + p;
        ull nd = dup2(sNq[r]);
#pragma unroll
        for (int q = 0; q < 4; q++) fmul2(acc[p][q], acc[p][q], nd);
        F4U o0, o1;
        o0.u[0] = acc[p][0]; o0.u[1] = acc[p][1];
        o1.u[0] = acc[p][2]; o1.u[1] = acc[p][3];
        float* orow = out + obase + (size_t)r * D;
        *(float4*)(orow + c0_)      = o0.f4;
        *(float4*)(orow + 64 + c0_) = o1.f4;
    }
}

extern "C" void kernel_launch(void* const* d_in, const int* in_sizes, int n_in,
                              void* d_out, int out_size)
{
    const float* x   = (const float*)d_in[0];
    const float* Pi  = (const float*)d_in[1];
    const float* cen = (const float*)d_in[2];
    const float* bnd = (const float*)d_in[3];
    float* out = (float*)d_out;

    const int n_rows = in_sizes[0] / D;        // 262144
    const int blocks = n_rows / ROWS;          // 2048

    const size_t smem = SMEM_FLOATS * sizeof(float);
    cudaFuncSetAttribute(tq_kernel, cudaFuncAttributeMaxDynamicSharedMemorySize, (int)smem);
    tq_kernel<<<blocks, TPB, smem>>>(x, Pi, cen, bnd, out);
}

// round 13
// speedup vs baseline: 1.8102x; 1.8102x over previous
#include <cuda_runtime.h>
#include <cuda_fp16.h>
#include <cuda_bf16.h>

#define D    128
#define TPB  256

// ---- smem byte offsets; all tiles 128 rows x 256B (32 KB), XOR-swizzled ----
#define SM_NQ    0         // 128 floats (fp16-roundtripped norms)
#define SM_PIHI  1024      // GEMM1 B: rows j, cols k   (Pi[j][k])
#define SM_PILO  33792
#define SM_PTHI  66560     // GEMM2 B: rows kk, cols j  (Pi[j][kk])
#define SM_PTLO  99328
#define SM_XHI   132096    // GEMM A: rows r, cols k / overlays V after GEMM1
#define SM_XLO   164864
#define SM_TOTAL 197632

typedef unsigned int u32;
typedef unsigned long long u64;

// swizzled byte offset inside a tile: row r (0..127), column-byte cb (0..255)
__device__ __forceinline__ int swz(int r, int cb) {
    return r * 256 + (((cb & ~15) ^ ((r & 7) << 4)) | (cb & 15));
}
__device__ __forceinline__ int swz16(int r, int cb) {   // cb 16B-aligned
    return r * 256 + (cb ^ ((r & 7) << 4));
}
// pack (a -> low half, b -> high half) into bf16x2 word
__device__ __forceinline__ u32 pk2(float a, float b) {
    u32 r; asm("cvt.rn.bf16x2.f32 %0, %1, %2;" : "=r"(r) : "f"(b), "f"(a)); return r;
}
__device__ __forceinline__ void split2(float v, float& hi, float& lo) {
    hi = __bfloat162float(__float2bfloat16_rn(v));
    lo = v - hi;
}
__device__ __forceinline__ u32 smem_u32(const void* p) {
    u32 a;
    asm("{ .reg .u64 t; cvta.to.shared.u64 t, %1; cvt.u32.u64 %0, t; }" : "=r"(a) : "l"(p));
    return a;
}
__device__ __forceinline__ void ldsm4(u32 r[4], u32 a) {
    asm volatile("ldmatrix.sync.aligned.m8n8.x4.shared.b16 {%0,%1,%2,%3}, [%4];"
                 : "=r"(r[0]), "=r"(r[1]), "=r"(r[2]), "=r"(r[3]) : "r"(a));
}
__device__ __forceinline__ void mma16816(float* c, const u32* a, u32 b0, u32 b1) {
    asm volatile("mma.sync.aligned.m16n8k16.row.col.f32.bf16.bf16.f32 "
                 "{%0,%1,%2,%3},{%4,%5,%6,%7},{%8,%9},{%0,%1,%2,%3};"
                 : "+f"(c[0]), "+f"(c[1]), "+f"(c[2]), "+f"(c[3])
                 : "r"(a[0]), "r"(a[1]), "r"(a[2]), "r"(a[3]), "r"(b0), "r"(b1));
}

// ---------- prep kernel: split Pi into 4 pre-swizzled bf16 tiles ----------
// gPibuf: [0]=Pi-hi  [32K]=Pi-lo  [64K]=PiT-hi  [96K]=PiT-lo
__device__ __align__(16) unsigned char gPibuf[131072];

__global__ void __launch_bounds__(256) prep_kernel(const float* __restrict__ Pi) {
    int idx = blockIdx.x * 256 + threadIdx.x;   // 8192 = 128 rows x 64 pairs
    int r = idx >> 6, p = idx & 63;
    // GEMM1 B tile: rows j=r, cols k: pair (2p, 2p+1)
    {
        float a = Pi[r * D + 2 * p], b = Pi[r * D + 2 * p + 1];
        float ah, al, bh, bl; split2(a, ah, al); split2(b, bh, bl);
        int off = swz(r, 4 * p);
        *(u32*)(gPibuf +         off) = pk2(ah, bh);
        *(u32*)(gPibuf + 32768 + off) = pk2(al, bl);
    }
    // GEMM2 B tile: rows kk=r, cols j: pair (2p, 2p+1) -> Pi[j][kk]
    {
        float a = Pi[(2 * p) * D + r], b = Pi[(2 * p + 1) * D + r];
        float ah, al, bh, bl; split2(a, ah, al); split2(b, bh, bl);
        int off = swz(r, 4 * p);
        *(u32*)(gPibuf + 65536 + off) = pk2(ah, bh);
        *(u32*)(gPibuf + 98304 + off) = pk2(al, bl);
    }
}

// ---------- shared GEMM core: c[2][8][4] += A(128x128) x B^T tiles ----------
__device__ __forceinline__ void gemm_ss(float c[2][8][4], u32 Ah, u32 Al,
                                        u32 Bh, u32 Bl, int mw, int nw, int lid) {
    const int arow  = 32 * mw + (lid & 15);
    const int brow  = 64 * nw + (lid & 15);
    const int koff  = (lid >> 4) << 4;
#pragma unroll
    for (int k8 = 0; k8 < 8; k8++) {
        const int kb = 32 * k8 + koff;
        u32 ah0[4], ah1[4], al0[4], al1[4];
        ldsm4(ah0, Ah + swz16(arow,      kb));
        ldsm4(ah1, Ah + swz16(arow + 16, kb));
        ldsm4(al0, Al + swz16(arow,      kb));
        ldsm4(al1, Al + swz16(arow + 16, kb));
#pragma unroll
        for (int ntp = 0; ntp < 4; ntp++) {
            u32 bh[4], bl[4];
            ldsm4(bh, Bh + swz16(brow + 16 * ntp, kb));
            ldsm4(bl, Bl + swz16(brow + 16 * ntp, kb));
            // even n-tile uses {b[0],b[2]}, odd uses {b[1],b[3]}
            mma16816(c[0][2*ntp],   ah0, bh[0], bh[2]);
            mma16816(c[0][2*ntp],   ah0, bl[0], bl[2]);
            mma16816(c[0][2*ntp],   al0, bh[0], bh[2]);
            mma16816(c[0][2*ntp+1], ah0, bh[1], bh[3]);
            mma16816(c[0][2*ntp+1], ah0, bl[1], bl[3]);
            mma16816(c[0][2*ntp+1], al0, bh[1], bh[3]);
            mma16816(c[1][2*ntp],   ah1, bh[0], bh[2]);
            mma16816(c[1][2*ntp],   ah1, bl[0], bl[2]);
            mma16816(c[1][2*ntp],   al1, bh[0], bh[2]);
            mma16816(c[1][2*ntp+1], ah1, bh[1], bh[3]);
            mma16816(c[1][2*ntp+1], ah1, bl[1], bl[3]);
            mma16816(c[1][2*ntp+1], al1, bh[1], bh[3]);
        }
    }
}

// ---------- main kernel ----------
__global__ void __launch_bounds__(TPB, 1)
tq_main(const float* __restrict__ x, const float* __restrict__ cen,
        const float* __restrict__ bnd, float* __restrict__ out)
{
    extern __shared__ unsigned char sm[];
    const u32 smb = smem_u32(sm);
    float* sNq = (float*)(sm + SM_NQ);
    const int tid = threadIdx.x;
    const int wid = tid >> 5, lid = tid & 31;
    const int mw = wid & 3, nw = wid >> 2;

    // 1) copy 4 pre-split Pi tiles (128 KB contiguous) gmem -> smem
    {
        const uint4* src = (const uint4*)gPibuf;
        uint4* dst = (uint4*)(sm + SM_PIHI);
#pragma unroll
        for (int i = 0; i < 32; i++) dst[tid + i * TPB] = src[tid + i * TPB];
    }

    // 2) x tile: norm, normalize, bf16 split, swizzled store [r][k]
    {
        const int r = tid >> 1, h = tid & 1;
        const float4* xr = (const float4*)(x + ((size_t)blockIdx.x * D + r) * D + h * 64);
        float4 xv[16];
        float ss = 0.f;
#pragma unroll
        for (int i = 0; i < 16; i++) {
            xv[i] = xr[i];
            ss += xv[i].x * xv[i].x + xv[i].y * xv[i].y
                + xv[i].z * xv[i].z + xv[i].w * xv[i].w;
        }
        ss += __shfl_xor_sync(0xffffffffu, ss, 1);
        float norm = sqrtf(ss);
        float invn = 1.0f / (norm + 1e-8f);
        if (h == 0) sNq[r] = __half2float(__float2half(norm));
#pragma unroll
        for (int i = 0; i < 16; i++) {
            float a0 = xv[i].x * invn, a1 = xv[i].y * invn;
            float a2 = xv[i].z * invn, a3 = xv[i].w * invn;
            float h0,l0,h1,l1,h2,l2,h3,l3;
            split2(a0,h0,l0); split2(a1,h1,l1); split2(a2,h2,l2); split2(a3,h3,l3);
            int cb = h * 128 + 8 * i;             // byte col of this float4
            int off = swz(r, cb);
            *(uint2*)(sm + SM_XHI + off) = make_uint2(pk2(h0,h1), pk2(h2,h3));
            *(uint2*)(sm + SM_XLO + off) = make_uint2(pk2(l0,l1), pk2(l2,l3));
        }
    }
    __syncthreads();

    // 3) GEMM1: rotated = Xu @ Pi^T   (3-term split-bf16)
    float c[2][8][4];
#pragma unroll
    for (int a = 0; a < 2; a++)
#pragma unroll
        for (int b = 0; b < 8; b++)
#pragma unroll
            for (int q = 0; q < 4; q++) c[a][b][q] = 0.f;

    gemm_ss(c, smb + SM_XHI, smb + SM_XLO, smb + SM_PIHI, smb + SM_PILO, mw, nw, lid);
    __syncthreads();   // everyone done reading X before V overlay

    // codebook -> registers (deferred to keep GEMM1 reg pressure low)
    float B[15], Dl[15];
    const float c0v = cen[0];
    {
        float prev = c0v;
#pragma unroll
        for (int i = 0; i < 15; i++) {
            B[i] = bnd[i + 1];
            float cc = cen[i + 1];
            Dl[i] = cc - prev; prev = cc;
        }
    }

    // 4) quantize (searchsorted-left over interior boundaries) + split V to smem
#pragma unroll
    for (int mt = 0; mt < 2; mt++) {
        const int row0 = 32 * mw + 16 * mt + (lid >> 2);
#pragma unroll
        for (int nt = 0; nt < 8; nt++) {
            const int cb = 128 * nw + 16 * nt + 4 * (lid & 3);   // byte col of pair
#pragma unroll
            for (int hp = 0; hp < 2; hp++) {
                const int row = row0 + 8 * hp;
                float v0 = c[mt][nt][2 * hp], v1 = c[mt][nt][2 * hp + 1];
                float w0 = c0v, w1 = c0v;
#pragma unroll
                for (int i = 0; i < 15; i++) {
                    if (v0 > B[i]) w0 += Dl[i];
                    if (v1 > B[i]) w1 += Dl[i];
                }
                float h0,l0,h1,l1;
                split2(w0,h0,l0); split2(w1,h1,l1);
                int off = swz(row, cb);
                *(u32*)(sm + SM_XHI + off) = pk2(h0, h1);
                *(u32*)(sm + SM_XLO + off) = pk2(l0, l1);
            }
        }
    }
    __syncthreads();

    // 5) GEMM2: recon = V @ Pi   (B tile = PiT, K-dim = j)
#pragma unroll
    for (int a = 0; a < 2; a++)
#pragma unroll
        for (int b = 0; b < 8; b++)
#pragma unroll
            for (int q = 0; q < 4; q++) c[a][b][q] = 0.f;

    gemm_ss(c, smb + SM_XHI, smb + SM_XLO, smb + SM_PTHI, smb + SM_PTLO, mw, nw, lid);

    // 6) epilogue: scale by fp16-roundtripped norm, store float2
    const size_t obase = (size_t)blockIdx.x * D * D;
#pragma unroll
    for (int mt = 0; mt < 2; mt++) {
        const int row0 = 32 * mw + 16 * mt + (lid >> 2);
        const float nq0 = sNq[row0], nq1 = sNq[row0 + 8];
#pragma unroll
        for (int nt = 0; nt < 8; nt++) {
            const int col = 64 * nw + 8 * nt + 2 * (lid & 3);
            float2 o0 = make_float2(c[mt][nt][0] * nq0, c[mt][nt][1] * nq0);
            float2 o1 = make_float2(c[mt][nt][2] * nq1, c[mt][nt][3] * nq1);
            *(float2*)(out + obase + (size_t)row0 * D + col)       = o0;
            *(float2*)(out + obase + (size_t)(row0 + 8) * D + col) = o1;
        }
    }
}

extern "C" void kernel_launch(void* const* d_in, const int* in_sizes, int n_in,
                              void* d_out, int out_size)
{
    const float* x   = (const float*)d_in[0];
    const float* Pi  = (const float*)d_in[1];
    const float* cen = (const float*)d_in[2];
    const float* bnd = (const float*)d_in[3];
    float* out = (float*)d_out;

    const int n_rows = in_sizes[0] / D;        // 262144
    const int blocks = n_rows / D;             // 2048

    prep_kernel<<<32, 256>>>(Pi);

    cudaFuncSetAttribute(tq_main, cudaFuncAttributeMaxDynamicSharedMemorySize, SM_TOTAL);
    tq_main<<<blocks, TPB, SM_TOTAL>>>(x, cen, bnd, out);
}